// round 15
// baseline (speedup 1.0000x reference)
#include <cuda_runtime.h>
#include <cstddef>

#define BATCH 16
#define NPB   262144                  // 512*512 elements per batch image
#define TAU_F 0.1f
#define SMOOTH_F 0.1f
#define THREADS 512
#define C_BLOCKS 176                  // contrastive blocks
#define D_BLOCKS 120                  // dice streaming blocks
#define GRID_ALL (C_BLOCKS + D_BLOCKS)   // 296 = 2 per SM
#define TILE 128
#define NTILES (NPB / TILE)           // 2048
#define ROWLEN 132                    // 128 + 4 pad (16B-aligned, conflict-free)
#define NV4 ((BATCH * NPB) / 4)       // 1048576 float4 granules

#define DEPTH 3
#define RAW_STAGE 6144                // floats: 3 arrays * 16 batches * 128
#define RAW_STAGE_B (RAW_STAGE * 4)   // 24576 bytes
#define RAW_BYTES (DEPTH * RAW_STAGE_B)  // 73728 bytes dynamic smem

// Global accumulators. Zero at module load; fused finalize re-zeroes after
// consuming, so every launch/graph replay starts from zero state.
__device__ float g_cross[BATCH * BATCH];
__device__ float g_sq1[BATCH];
__device__ float g_sq2[BATCH];
__device__ float g_pos[BATCH];
__device__ float g_dice[3];
__device__ unsigned int g_done;

__device__ __forceinline__ float sigf(float x) {
    float e = __expf(-x);
    float r;
    asm("rcp.approx.f32 %0, %1;" : "=f"(r) : "f"(1.0f + e));
    return r;
}

__device__ __forceinline__ void cp16(unsigned int dst, const float* src) {
    asm volatile("cp.async.cg.shared.global [%0], [%1], 16;"
                 :: "r"(dst), "l"(src) : "memory");
}

__global__ void __launch_bounds__(THREADS, 2)
main_kernel(const float* __restrict__ pred, const float* __restrict__ gt,
            const float* __restrict__ in1,  const float* __restrict__ in2,
            const float* __restrict__ msk,
            float* __restrict__ out, int out_size)
{
    extern __shared__ float raw[];                 // [DEPTH][3][16][128]
    __shared__ float s1_sh[BATCH * ROWLEN];
    __shared__ float s2_sh[BATCH * ROWLEN];
    __shared__ unsigned int s_islast;

    const int tid  = threadIdx.x;
    const int lane = tid & 31;
    const int w    = tid >> 5;          // warp id 0..15

    if ((int)blockIdx.x < C_BLOCKS) {
        // ================== CONTRASTIVE PATH ==================
        const int b = w;                // warp w owns batch b in Phase A
        // gmem pointers offset to this thread's (batch, float4 slot)
        const size_t boff = (size_t)b * NPB + (size_t)(lane * 4);
        const float* p1 = in1 + boff;
        const float* p2 = in2 + boff;
        const float* pm = msk + boff;

        // this thread's cp.async dst offset inside an array block
        const unsigned int raw_u32 =
            (unsigned int)__cvta_generic_to_shared(raw) +
            (unsigned int)((b * TILE + lane * 4) * 4);

        // Phase B: warp w owns a disjoint 4x4 Gram block
        const int b1b = (w & 3) * 4;
        const int b2b = (w >> 2) * 4;
        const int cb  = lane * 4;       // K float4 slot

        float c[4][4];
#pragma unroll
        for (int i = 0; i < 4; i++)
#pragma unroll
            for (int jj = 0; jj < 4; jj++) c[i][jj] = 0.0f;

        float sq1a = 0.0f, sq2a = 0.0f, posa = 0.0f;

        // ---- fetch one stage (3 cp.async per thread); always commit ----
        auto fetch = [&](int tk, int buf) {
            if (tk < NTILES) {
                const size_t g = (size_t)tk * TILE;
                const unsigned int base = raw_u32 + (unsigned int)(buf * RAW_STAGE_B);
                cp16(base,          p1 + g);
                cp16(base +  8192u, p2 + g);
                cp16(base + 16384u, pm + g);
            }
            asm volatile("cp.async.commit_group;");
        };

        // Prologue (every contrastive block has >= 11 tiles)
        fetch((int)blockIdx.x,                0);
        fetch((int)blockIdx.x + C_BLOCKS,     1);
        fetch((int)blockIdx.x + 2 * C_BLOCKS, 2);

        int k = 0;
        for (int tk = blockIdx.x; tk < NTILES; tk += C_BLOCKS, k++) {
            int buf = k % DEPTH;
            asm volatile("cp.async.wait_group 2;");   // oldest stage delivered
            __syncthreads();                          // visible + prior Phase B done

            // ---- Phase A: raw smem -> regs, sigmoid, stage, pointwise accum ----
            const float* rb = raw + buf * RAW_STAGE + b * TILE + lane * 4;
            const float4 x1 = *(const float4*)(rb);
            const float4 x2 = *(const float4*)(rb + 2048);
            const float4 mm = *(const float4*)(rb + 4096);

            float4 s1v, s2v;
            s1v.x = sigf(x1.x); s1v.y = sigf(x1.y); s1v.z = sigf(x1.z); s1v.w = sigf(x1.w);
            s2v.x = sigf(x2.x); s2v.y = sigf(x2.y); s2v.z = sigf(x2.z); s2v.w = sigf(x2.w);
            *(float4*)&s1_sh[b * ROWLEN + lane * 4] = s1v;
            *(float4*)&s2_sh[b * ROWLEN + lane * 4] = s2v;

            {
                const float s1a[4] = {s1v.x, s1v.y, s1v.z, s1v.w};
                const float s2a[4] = {s2v.x, s2v.y, s2v.z, s2v.w};
                const float mv[4]  = {mm.x, mm.y, mm.z, mm.w};
#pragma unroll
                for (int kk = 0; kk < 4; kk++) {
                    const float d = mv[kk] * (s1a[kk] - s2a[kk]);
                    posa = fmaf(d, d, posa);
                    sq1a = fmaf(s1a[kk], s1a[kk], sq1a);
                    sq2a = fmaf(s2a[kk], s2a[kk], sq2a);
                }
            }
            __syncthreads();           // staged ready; raw[buf] fully consumed

            // Refill this stage for tile k+DEPTH (overlaps Phase B + next wait)
            fetch(tk + DEPTH * C_BLOCKS, buf);

            // ---- Phase B: 4x4 Gram block (8 LDS.128/lane, conflict-free) ----
            float4 av[4];
#pragma unroll
            for (int i = 0; i < 4; i++)
                av[i] = *(const float4*)&s1_sh[(b1b + i) * ROWLEN + cb];
#pragma unroll
            for (int jj = 0; jj < 4; jj++) {
                const float4 bv = *(const float4*)&s2_sh[(b2b + jj) * ROWLEN + cb];
#pragma unroll
                for (int i = 0; i < 4; i++) {
                    c[i][jj] = fmaf(av[i].x, bv.x, c[i][jj]);
                    c[i][jj] = fmaf(av[i].y, bv.y, c[i][jj]);
                    c[i][jj] = fmaf(av[i].z, bv.z, c[i][jj]);
                    c[i][jj] = fmaf(av[i].w, bv.w, c[i][jj]);
                }
            }
        }

        // ---- Reductions (full-warp shuffles, unconditional) ----
#pragma unroll
        for (int i = 0; i < 4; i++) {
#pragma unroll
            for (int jj = 0; jj < 4; jj++) {
                float v = c[i][jj];
                v += __shfl_xor_sync(0xffffffffu, v, 16);
                v += __shfl_xor_sync(0xffffffffu, v, 8);
                v += __shfl_xor_sync(0xffffffffu, v, 4);
                v += __shfl_xor_sync(0xffffffffu, v, 2);
                v += __shfl_xor_sync(0xffffffffu, v, 1);
                if (lane == 0) atomicAdd(&g_cross[(b1b + i) * BATCH + (b2b + jj)], v);
            }
        }
#pragma unroll
        for (int off = 16; off >= 1; off >>= 1) {
            posa += __shfl_xor_sync(0xffffffffu, posa, off);
            sq1a += __shfl_xor_sync(0xffffffffu, sq1a, off);
            sq2a += __shfl_xor_sync(0xffffffffu, sq2a, off);
        }
        if (lane == 0) {
            atomicAdd(&g_pos[b], posa);
            atomicAdd(&g_sq1[b], sq1a);
            atomicAdd(&g_sq2[b], sq2a);
        }
    } else {
        // ================== DICE STREAMING PATH (no barriers) ==================
        const float4* pred4 = (const float4*)pred;
        const float4* gt4   = (const float4*)gt;
        float dP = 0.0f, dG = 0.0f, dPG = 0.0f;

        const int gid    = ((int)blockIdx.x - C_BLOCKS) * THREADS + tid;
        const int stride = D_BLOCKS * THREADS;
#pragma unroll 4
        for (int i = gid; i < NV4; i += stride) {
            const float4 pp = pred4[i];
            const float4 gg = gt4[i];
            const float sv[4] = {sigf(pp.x), sigf(pp.y), sigf(pp.z), sigf(pp.w)};
            const float gv[4] = {gg.x, gg.y, gg.z, gg.w};
#pragma unroll
            for (int kk = 0; kk < 4; kk++) {
                dP  += sv[kk];
                dG  += gv[kk];
                dPG = fmaf(sv[kk], gv[kk], dPG);
            }
        }
#pragma unroll
        for (int off = 16; off >= 1; off >>= 1) {
            dP  += __shfl_xor_sync(0xffffffffu, dP,  off);
            dG  += __shfl_xor_sync(0xffffffffu, dG,  off);
            dPG += __shfl_xor_sync(0xffffffffu, dPG, off);
        }
        if (lane == 0) {
            atomicAdd(&g_dice[0], dP);
            atomicAdd(&g_dice[1], dG);
            atomicAdd(&g_dice[2], dPG);
        }
    }

    // ---- Last-block fused finalize ----
    __threadfence();
    if (tid == 0)
        s_islast = (atomicAdd(&g_done, 1u) == (unsigned)(GRID_ALL - 1));
    __syncthreads();
    if (!s_islast) return;

    {
        float* s_simneg = s1_sh;           // reuse staged smem
        float* s_loss   = s1_sh + BATCH;
        float* s_dice   = s1_sh + 2 * BATCH;

        const int b1 = tid >> 4;
        const int b2 = tid & 15;
        const float invN = 1.0f / (float)NPB;

        float sim = 0.0f;
        float r_pos = 0.0f;
        if (tid < 256) {                   // warps 0-7 fully active: shuffles safe
            const float r_cross = __ldcg(&g_cross[tid]);
            const float r_sq1   = __ldcg(&g_sq1[b1]);
            const float r_sq2   = __ldcg(&g_sq2[b2]);
            if (tid < BATCH) r_pos = __ldcg(&g_pos[tid]);
            if (tid < 3) s_dice[tid] = __ldcg(&g_dice[tid]);

            const float mse = (r_sq1 + r_sq2 - 2.0f * r_cross) * invN;
            sim = expf(-mse / TAU_F);
            if (b1 == b2) sim = 0.0f;
#pragma unroll
            for (int off = 8; off >= 1; off >>= 1)
                sim += __shfl_xor_sync(0xffffffffu, sim, off);
        }
        __syncthreads();
        if (tid < 256 && b2 == 0) s_simneg[b1] = sim;

        // Re-zero state for next graph replay
        if (tid < 256) g_cross[tid] = 0.0f;
        if (tid < BATCH) { g_pos[tid] = 0.0f; g_sq1[tid] = 0.0f; g_sq2[tid] = 0.0f; }
        if (tid < 3) g_dice[tid] = 0.0f;
        if (tid == 0) g_done = 0u;
        __syncthreads();

        if (tid < BATCH) {
            const float simpos = expf(-(r_pos * invN) / TAU_F);
            s_loss[tid] = -logf(simpos / (simpos + s_simneg[tid]));
        }
        __syncthreads();

        if (tid == 0) {
            float l = 0.0f;
#pragma unroll
            for (int i = 0; i < BATCH; i++) l += s_loss[i];
            const float contrast = l * (1.0f / (float)BATCH);
            const float dice = 1.0f - (2.0f * s_dice[2] + SMOOTH_F) /
                                      (s_dice[0] + s_dice[1] + SMOOTH_F);
            out[0] = dice + contrast;
            if (out_size > 1) out[1] = dice;
            if (out_size > 2) out[2] = 0.0f;
            if (out_size > 3) out[3] = contrast;
        }
    }
}

extern "C" void kernel_launch(void* const* d_in, const int* in_sizes, int n_in,
                              void* d_out, int out_size) {
    const float* pred = (const float*)d_in[0];
    const float* gt   = (const float*)d_in[1];
    const float* in1  = (const float*)d_in[2];
    const float* in2  = (const float*)d_in[3];
    const float* msk  = (const float*)d_in[4];
    float* out = (float*)d_out;

    cudaFuncSetAttribute(main_kernel,
                         cudaFuncAttributeMaxDynamicSharedMemorySize, RAW_BYTES);
    main_kernel<<<GRID_ALL, THREADS, RAW_BYTES>>>(pred, gt, in1, in2, msk, out, out_size);
}